// round 2
// baseline (speedup 1.0000x reference)
#include <cuda_runtime.h>
#include <math.h>

// CT forward projection:
// out[r] = sum_k  volume[floor(M @ (src + tmid*diff) + b)] * (t1-t0)*|diff|
// for finite segment pairs (t0,t1) = (tvals[r,k], tvals[r,k+1]), in-bounds voxels.
//
// Strategy: one warp per ray. Lanes cover segments base+lane, 32 per iteration.
// tvals loads are coalesced. Sorted tvals with +inf padding => uniform warp
// early-exit when the block-lead t is inf. Per-lane accumulate, warp-reduce.

__global__ __launch_bounds__(256)
void ctproj_kernel(const float* __restrict__ volume,
                   const float* __restrict__ tvals,
                   const float* __restrict__ src,
                   const float* __restrict__ dst,
                   const float* __restrict__ Mmat,
                   const float* __restrict__ bvec,
                   float* __restrict__ out,
                   int R, int K, int n)
{
    const int warp = (blockIdx.x * blockDim.x + threadIdx.x) >> 5;
    const int lane = threadIdx.x & 31;
    if (warp >= R) return;
    const int r = warp;

    const float INF = __int_as_float(0x7f800000);

    // Per-ray geometry (broadcast loads, same line for all lanes)
    const float sx = __ldg(src + 3 * r + 0);
    const float sy = __ldg(src + 3 * r + 1);
    const float sz = __ldg(src + 3 * r + 2);
    const float dx = __ldg(dst + 3 * r + 0) - sx;
    const float dy = __ldg(dst + 3 * r + 1) - sy;
    const float dz = __ldg(dst + 3 * r + 2) - sz;
    const float ray_len = sqrtf(dx * dx + dy * dy + dz * dz);

    // Transform (tiny, L2-resident)
    const float m00 = __ldg(Mmat + 0), m01 = __ldg(Mmat + 1), m02 = __ldg(Mmat + 2);
    const float m10 = __ldg(Mmat + 3), m11 = __ldg(Mmat + 4), m12 = __ldg(Mmat + 5);
    const float m20 = __ldg(Mmat + 6), m21 = __ldg(Mmat + 7), m22 = __ldg(Mmat + 8);
    const float b0 = __ldg(bvec + 0), b1 = __ldg(bvec + 1), b2 = __ldg(bvec + 2);

    const float* __restrict__ trow = tvals + (size_t)r * K;
    const int nseg = K - 1;
    const unsigned nu = (unsigned)n;

    float acc = 0.0f;

    for (int base = 0; base < nseg; base += 32) {
        const int k = base + lane;
        // Coalesced loads of the t window. k <= base+31 <= nseg (=K-1) is a
        // valid index into trow (K elements); t1 needs k+1 <= K-1 i.e. k < nseg.
        const float t0 = __ldg(trow + k);
        const float t1 = (k < nseg) ? __ldg(trow + k + 1) : INF;

        // Uniform early exit: tvals sorted ascending with +inf tail, so if the
        // block-minimum t0 (lane 0) is inf, every later segment is inf too.
        const float t0_lead = __shfl_sync(0xffffffffu, t0, 0);
        if (!(t0_lead < 1e30f)) break;

        // finite(t1) implies finite(t0) (sorted, inf only at tail)
        const bool fin = (k < nseg) && (t1 < 1e30f);

        const float seg  = (t1 - t0) * ray_len;
        const float tmid = 0.5f * (t0 + t1);

        const float px = fmaf(tmid, dx, sx);
        const float py = fmaf(tmid, dy, sy);
        const float pz = fmaf(tmid, dz, sz);

        const float qx = fmaf(m00, px, fmaf(m01, py, fmaf(m02, pz, b0)));
        const float qy = fmaf(m10, px, fmaf(m11, py, fmaf(m12, pz, b1)));
        const float qz = fmaf(m20, px, fmaf(m21, py, fmaf(m22, pz, b2)));

        const int ix = (int)floorf(qx);
        const int iy = (int)floorf(qy);
        const int iz = (int)floorf(qz);

        const bool inb = fin &&
                         ((unsigned)ix < nu) &&
                         ((unsigned)iy < nu) &&
                         ((unsigned)iz < nu);

        if (inb) {
            const size_t idx = ((size_t)ix * n + iy) * n + iz;
            acc = fmaf(__ldg(volume + idx), seg, acc);
        }
    }

    // Warp reduction
    #pragma unroll
    for (int off = 16; off > 0; off >>= 1)
        acc += __shfl_down_sync(0xffffffffu, acc, off);

    if (lane == 0) out[r] = acc;
}

extern "C" void kernel_launch(void* const* d_in, const int* in_sizes, int n_in,
                              void* d_out, int out_size)
{
    const float* volume = (const float*)d_in[0];
    const float* tvals  = (const float*)d_in[1];
    const float* src    = (const float*)d_in[2];
    const float* dst    = (const float*)d_in[3];
    const float* Mmat   = (const float*)d_in[4];
    const float* bvec   = (const float*)d_in[5];
    float* out = (float*)d_out;

    const int R = in_sizes[2] / 3;          // src is (R,3)
    const int K = in_sizes[1] / R;          // tvals is (R,K)
    // volume is (n,n,n)
    int n = (int)lroundf(cbrtf((float)in_sizes[0]));
    while ((long long)n * n * n < (long long)in_sizes[0]) n++;
    while ((long long)n * n * n > (long long)in_sizes[0]) n--;

    const int threads = 256;                 // 8 warps/block = 8 rays/block
    const int warps_needed = R;
    const int blocks = (warps_needed * 32 + threads - 1) / threads;

    ctproj_kernel<<<blocks, threads>>>(volume, tvals, src, dst, Mmat, bvec,
                                       out, R, K, n);
}

// round 3
// speedup vs baseline: 1.6016x; 1.6016x over previous
#include <cuda_runtime.h>
#include <math.h>

// CT forward projection, warp-per-ray, 128 segments per warp-iteration.
// Lane loads float4 of tvals -> 4 independent volume gathers in flight
// (MLP=4/warp). Affine transform folded per-ray: q(t) = S + t*D where
// S = M@src + b, D = M@diff. Branchless segment predication.

__global__ __launch_bounds__(256)
void ctproj_kernel(const float* __restrict__ volume,
                   const float* __restrict__ tvals,
                   const float* __restrict__ src,
                   const float* __restrict__ dst,
                   const float* __restrict__ Mmat,
                   const float* __restrict__ bvec,
                   float* __restrict__ out,
                   int R, int K, int n)
{
    const int warp = (blockIdx.x * blockDim.x + threadIdx.x) >> 5;
    const int lane = threadIdx.x & 31;
    if (warp >= R) return;
    const int r = warp;

    // Per-ray geometry (broadcast loads)
    const float sx = __ldg(src + 3 * r + 0);
    const float sy = __ldg(src + 3 * r + 1);
    const float sz = __ldg(src + 3 * r + 2);
    const float dx = __ldg(dst + 3 * r + 0) - sx;
    const float dy = __ldg(dst + 3 * r + 1) - sy;
    const float dz = __ldg(dst + 3 * r + 2) - sz;
    const float ray_len = sqrtf(dx * dx + dy * dy + dz * dz);

    const float m00 = __ldg(Mmat + 0), m01 = __ldg(Mmat + 1), m02 = __ldg(Mmat + 2);
    const float m10 = __ldg(Mmat + 3), m11 = __ldg(Mmat + 4), m12 = __ldg(Mmat + 5);
    const float m20 = __ldg(Mmat + 6), m21 = __ldg(Mmat + 7), m22 = __ldg(Mmat + 8);
    const float b0 = __ldg(bvec + 0), b1 = __ldg(bvec + 1), b2 = __ldg(bvec + 2);

    // Fold transform: q(t) = S + t * D
    const float Sx = m00 * sx + m01 * sy + m02 * sz + b0;
    const float Sy = m10 * sx + m11 * sy + m12 * sz + b1;
    const float Sz = m20 * sx + m21 * sy + m22 * sz + b2;
    const float Dx = m00 * dx + m01 * dy + m02 * dz;
    const float Dy = m10 * dx + m11 * dy + m12 * dz;
    const float Dz = m20 * dx + m21 * dy + m22 * dz;

    const float* __restrict__ trow = tvals + (size_t)r * K;
    const int nseg = K - 1;
    const int nm1  = n - 1;
    const unsigned nu = (unsigned)n;
    const unsigned FULL = 0xffffffffu;

    float acc0 = 0.0f, acc1 = 0.0f;

    for (int base = 0; base < nseg; base += 128) {
        const int i = base + 4 * lane;           // first t index this lane owns
        // float4 load: i+3 <= base+127 <= nseg-? ; for K=512, max i+3 = 511 < K.
        const float4 v = *(const float4*)(trow + i);

        // Uniform early exit: t sorted ascending with +inf tail. If lane0's
        // t[base] is inf, all 128 segments of this block are padding.
        const float lead = __shfl_sync(FULL, v.x, 0);
        if (!(lead < 1e30f)) break;

        // t[i+4]: next lane's v.x; lane 31 takes the broadcast extra load.
        const int eidx = (base + 128 < K) ? (base + 128) : (K - 1);
        const float extra = __ldg(trow + eidx);
        float t4 = __shfl_down_sync(FULL, v.x, 1);
        if (lane == 31) t4 = extra;

        const float t[5] = { v.x, v.y, v.z, v.w, t4 };

        int   idx[4];
        float w[4];

        #pragma unroll
        for (int j = 0; j < 4; ++j) {
            const int  k     = i + j;
            const bool valid = (k < nseg) && (t[j + 1] < 1e30f);

            const float seg  = (t[j + 1] - t[j]) * ray_len;
            const float tm   = 0.5f * (t[j] + t[j + 1]);

            const float qx = fmaf(tm, Dx, Sx);
            const float qy = fmaf(tm, Dy, Sy);
            const float qz = fmaf(tm, Dz, Sz);

            const int ix = (int)floorf(qx);
            const int iy = (int)floorf(qy);
            const int iz = (int)floorf(qz);

            const bool inb = valid &&
                             ((unsigned)ix < nu) &&
                             ((unsigned)iy < nu) &&
                             ((unsigned)iz < nu);

            const int cx = min(max(ix, 0), nm1);
            const int cy = min(max(iy, 0), nm1);
            const int cz = min(max(iz, 0), nm1);

            idx[j] = (cx * n + cy) * n + cz;
            w[j]   = inb ? seg : 0.0f;
        }

        // Batch the 4 independent gathers, then accumulate.
        float g0 = __ldg(volume + idx[0]);
        float g1 = __ldg(volume + idx[1]);
        float g2 = __ldg(volume + idx[2]);
        float g3 = __ldg(volume + idx[3]);

        acc0 = fmaf(g0, w[0], acc0);
        acc1 = fmaf(g1, w[1], acc1);
        acc0 = fmaf(g2, w[2], acc0);
        acc1 = fmaf(g3, w[3], acc1);
    }

    float acc = acc0 + acc1;
    #pragma unroll
    for (int off = 16; off > 0; off >>= 1)
        acc += __shfl_down_sync(FULL, acc, off);

    if (lane == 0) out[r] = acc;
}

extern "C" void kernel_launch(void* const* d_in, const int* in_sizes, int n_in,
                              void* d_out, int out_size)
{
    const float* volume = (const float*)d_in[0];
    const float* tvals  = (const float*)d_in[1];
    const float* src    = (const float*)d_in[2];
    const float* dst    = (const float*)d_in[3];
    const float* Mmat   = (const float*)d_in[4];
    const float* bvec   = (const float*)d_in[5];
    float* out = (float*)d_out;

    const int R = in_sizes[2] / 3;          // src is (R,3)
    const int K = in_sizes[1] / R;          // tvals is (R,K)
    int n = (int)lroundf(cbrtf((float)in_sizes[0]));
    while ((long long)n * n * n < (long long)in_sizes[0]) n++;
    while ((long long)n * n * n > (long long)in_sizes[0]) n--;

    const int threads = 256;                 // 8 warps = 8 rays per block
    const int blocks = (R * 32 + threads - 1) / threads;

    ctproj_kernel<<<blocks, threads>>>(volume, tvals, src, dst, Mmat, bvec,
                                       out, R, K, n);
}